// round 12
// baseline (speedup 1.0000x reference)
#include <cuda_runtime.h>

// CapsNet dynamic routing, factorized. 1 batch/CTA, T=512, 2 CTAs/SM.
// R12: immediate-offset addressing. c planes stride 1187 with u-stride 33
// (bank-spread without s-rotation); x stored [s][q=(fg,sh)][u] f4 with strides
// 153/38 (conflict-free, compile-time s offsets). No XOR swizzles.

namespace {
constexpr int O_ = 10, U_ = 36, E_ = 16, F_ = 8;
constexpr int N_ = 1152;
constexpr int B_ = 256;
constexpr int T_ = 512;              // 16 warps, 2 CTAs/SM
constexpr int PS = 1187;             // c plane stride (o-major), u-stride 33
constexpr int XQ = 38;               // x q-stride (f4 units)
constexpr int XS_ = 153;             // x s-stride (f4 units)

// shared layout (floats)
constexpr int OFF_XS = 0;                         // x: 16*153 f4 = 9792 floats
constexpr int OFF_C  = OFF_XS + 16 * XS_ * 4;     // c: 10 planes * 1187 = 11870
constexpr int OFF_P  = (OFF_C + O_ * PS + 3) & ~3;   // pb 720 f4 (16B aligned)
constexpr int OFF_VV = OFF_P + 2880;              // [O][E] 160
constexpr int SM_FLOATS = OFF_VV + 160;           // 24704 -> 98,816 B
} // namespace

__global__ __launch_bounds__(T_, 2)
void caps_route_kernel(const float* __restrict__ x,
                       const float* __restrict__ Wg,
                       float* __restrict__ out) {
    extern __shared__ float sm[];
    float* cc  = sm + OFF_C;
    float* pbf = sm + OFF_P;
    float* vv  = sm + OFF_VV;
    float4* xs4 = reinterpret_cast<float4*>(sm + OFF_XS);
    float4* pb4 = reinterpret_cast<float4*>(pbf);

    const int tid = threadIdx.x;
    const int b = blockIdx.x;
    const int warp = tid >> 5;
    const int lane = tid & 31;

    const float4* __restrict__ wp4 = reinterpret_cast<const float4*>(Wg);

    // ---- load x tile: gmem [n][f] -> smem [s][q=(fg*2+sh)][u] (f4 units) ----
    {
        const float4* xg = reinterpret_cast<const float4*>(x) + (size_t)b * (N_ * F_ / 4);
        #pragma unroll
        for (int i = tid; i < N_ * F_ / 4; i += T_) {
            const int n = i >> 1, fg = i & 1;
            const int u = n >> 5, sh = (n >> 4) & 1, s = n & 15;
            xs4[s * XS_ + (fg * 2 + sh) * XQ + u] = xg[i];
        }
    }
    __syncthreads();

    // P2 task decode (288 tasks): tid = u<<3 | oh<<2 | fg<<1 | sh  (sh = lane bit 0)
    const int p2_sh = tid & 1;
    const int p2_fg = (tid >> 1) & 1;
    const int p2_oh = (tid >> 2) & 1;
    const int p2_u  = tid >> 3;
    const float* p2_cb = cc + p2_oh * 5 * PS + p2_u * 33 + p2_sh * 16;
    const float4* p2_xb = xs4 + (p2_fg * 2 + p2_sh) * XQ + p2_u;
    float4* p2_pr = pb4 + (tid >> 1) * 5;    // task' = (u,oh,fg), sh reduced away

    // P3 decode: warp = o (<10); lane = e*2 + fh (lane-linear W)
    const int p3_e  = lane >> 1;
    const int p3_fh = lane & 1;

    // P5 decode
    const int p5_e  = lane >> 1;
    const int sel1 = (lane >> 1) & 1;
    const int sel2 = (lane >> 2) & 1;
    const int p5_f = (lane & 1) * 4 + sel1 * 2 + sel2;

    for (int it = 0; it < 4; ++it) {
        // ---- P2: y partials for (u,fg,oh); sh halves merged via shfl ----
        if (tid < 288) {
            float4 a0 = make_float4(0.f,0.f,0.f,0.f), a1 = a0, a2 = a0, a3 = a0, a4 = a0;
            if (it == 0) {
                #pragma unroll
                for (int j = 0; j < 16; ++j) {
                    const float4 xv = p2_xb[j * XS_];
                    a0.x += xv.x; a0.y += xv.y; a0.z += xv.z; a0.w += xv.w;
                }
                a0.x *= 0.1f; a0.y *= 0.1f; a0.z *= 0.1f; a0.w *= 0.1f;
                a1 = a0; a2 = a0; a3 = a0; a4 = a0;
            } else {
                #pragma unroll
                for (int j = 0; j < 16; ++j) {
                    const float4 xv = p2_xb[j * XS_];
                    const float c0 = p2_cb[j];
                    const float c1 = p2_cb[PS + j];
                    const float c2 = p2_cb[2 * PS + j];
                    const float c3 = p2_cb[3 * PS + j];
                    const float c4 = p2_cb[4 * PS + j];
                    a0.x += c0 * xv.x; a0.y += c0 * xv.y; a0.z += c0 * xv.z; a0.w += c0 * xv.w;
                    a1.x += c1 * xv.x; a1.y += c1 * xv.y; a1.z += c1 * xv.z; a1.w += c1 * xv.w;
                    a2.x += c2 * xv.x; a2.y += c2 * xv.y; a2.z += c2 * xv.z; a2.w += c2 * xv.w;
                    a3.x += c3 * xv.x; a3.y += c3 * xv.y; a3.z += c3 * xv.z; a3.w += c3 * xv.w;
                    a4.x += c4 * xv.x; a4.y += c4 * xv.y; a4.z += c4 * xv.z; a4.w += c4 * xv.w;
                }
            }
            // merge sh halves (lane bit 0)
            a0.x += __shfl_xor_sync(0xffffffffu, a0.x, 1);
            a0.y += __shfl_xor_sync(0xffffffffu, a0.y, 1);
            a0.z += __shfl_xor_sync(0xffffffffu, a0.z, 1);
            a0.w += __shfl_xor_sync(0xffffffffu, a0.w, 1);
            a1.x += __shfl_xor_sync(0xffffffffu, a1.x, 1);
            a1.y += __shfl_xor_sync(0xffffffffu, a1.y, 1);
            a1.z += __shfl_xor_sync(0xffffffffu, a1.z, 1);
            a1.w += __shfl_xor_sync(0xffffffffu, a1.w, 1);
            a2.x += __shfl_xor_sync(0xffffffffu, a2.x, 1);
            a2.y += __shfl_xor_sync(0xffffffffu, a2.y, 1);
            a2.z += __shfl_xor_sync(0xffffffffu, a2.z, 1);
            a2.w += __shfl_xor_sync(0xffffffffu, a2.w, 1);
            a3.x += __shfl_xor_sync(0xffffffffu, a3.x, 1);
            a3.y += __shfl_xor_sync(0xffffffffu, a3.y, 1);
            a3.z += __shfl_xor_sync(0xffffffffu, a3.z, 1);
            a3.w += __shfl_xor_sync(0xffffffffu, a3.w, 1);
            a4.x += __shfl_xor_sync(0xffffffffu, a4.x, 1);
            a4.y += __shfl_xor_sync(0xffffffffu, a4.y, 1);
            a4.z += __shfl_xor_sync(0xffffffffu, a4.z, 1);
            a4.w += __shfl_xor_sync(0xffffffffu, a4.w, 1);
            if (p2_sh == 0) {
                p2_pr[0] = a0; p2_pr[1] = a1; p2_pr[2] = a2; p2_pr[3] = a3; p2_pr[4] = a4;
            }
        }
        __syncthreads();

        // ---- P3 (+fused squash): warp=o, lane=(e,fh), lane-linear W ----
        if (warp < 10) {
            const int o = warp;
            const int oh = (o >= 5);
            const int k = o - 5 * oh;
            const int rbase = (oh * 2 + p3_fh) * 5 + k;
            float p0 = 0.f;
            #pragma unroll 12
            for (int u = 0; u < 36; ++u) {
                const float4 w = wp4[(o * 36 + u) * 32 + lane];   // contiguous 512B/warp
                const float4 A = pb4[u * 20 + rbase];
                p0 += w.x * A.x + w.y * A.y + w.z * A.z + w.w * A.w;
            }
            const float s0 = p0 + __shfl_xor_sync(0xffffffffu, p0, 1);
            float nsq0 = s0 * s0;
            #pragma unroll
            for (int m = 2; m <= 16; m <<= 1)
                nsq0 += __shfl_xor_sync(0xffffffffu, nsq0, m);
            if (p3_fh == 0) vv[o * 16 + p3_e] = s0 * (sqrtf(nsq0) / (1.f + nsq0));
        }
        __syncthreads();

        if (it == 3) break;

        // ---- P5: wv[o,u,f]; warp per (o,u), lane-linear W, shuffle-reduce e ----
        for (int task = warp; task < 360; task += 16) {
            const float4 w = wp4[task * 32 + lane];   // contiguous 512B/warp
            const int o = task / 36;
            const float ve0 = vv[o * 16 + p5_e];
            float P0[4] = {w.x * ve0, w.y * ve0, w.z * ve0, w.w * ve0};
            float k0a = P0[2 * sel1]     + __shfl_xor_sync(0xffffffffu, P0[2 * (sel1 ^ 1)],     2);
            float k0b = P0[2 * sel1 + 1] + __shfl_xor_sync(0xffffffffu, P0[2 * (sel1 ^ 1) + 1], 2);
            float r0 = (sel2 ? k0b : k0a) + __shfl_xor_sync(0xffffffffu, (sel2 ? k0a : k0b), 4);
            r0 += __shfl_xor_sync(0xffffffffu, r0, 8);
            r0 += __shfl_xor_sync(0xffffffffu, r0, 16);
            if (lane < 8) pbf[task * 8 + p5_f] = r0;
        }
        __syncthreads();

        // ---- P6: c <- normalize_o( c * exp(x . wv) ) ----
        #pragma unroll
        for (int kk = 0; kk < 3; ++kk) {
            const int n = tid + T_ * kk;
            if (n < N_) {
                const int u = n >> 5;
                const int sh = (n >> 4) & 1;
                const int s = n & 15;
                const float4 x0 = xs4[s * XS_ + sh * XQ + u];            // fg=0
                const float4 x1 = xs4[s * XS_ + (2 + sh) * XQ + u];      // fg=1
                const float4* wvb = pb4 + u * 2;
                float* cp = cc + u * 33 + sh * 16 + s;
                float t[O_];
                float ss = 0.f;
                if (it > 0) {
                    #pragma unroll
                    for (int o = 0; o < O_; ++o) t[o] = cp[o * PS];   // issue loads early
                }
                #pragma unroll
                for (int o = 0; o < O_; ++o) {
                    const float4 w0 = wvb[o * 72], w1 = wvb[o * 72 + 1];
                    const float d = x0.x * w0.x + x0.y * w0.y + x0.z * w0.z + x0.w * w0.w
                                  + x1.x * w1.x + x1.y * w1.y + x1.z * w1.z + x1.w * w1.w;
                    const float tv = (it == 0 ? 0.1f : t[o]) * __expf(d);
                    t[o] = tv;
                    ss += tv;
                }
                const float inv = 1.0f / ss;
                #pragma unroll
                for (int o = 0; o < O_; ++o) cp[o * PS] = t[o] * inv;
            }
        }
        __syncthreads();
    }

    // ---- write out[b][o][e] ----
    if (tid < O_ * E_) {
        out[(size_t)b * (O_ * E_) + tid] = vv[tid];
    }
}

extern "C" void kernel_launch(void* const* d_in, const int* in_sizes, int n_in,
                              void* d_out, int out_size) {
    (void)in_sizes; (void)n_in; (void)out_size;
    const float* x = (const float*)d_in[0];
    const float* W = (const float*)d_in[1];
    float* out = (float*)d_out;

    const size_t smem = (size_t)SM_FLOATS * sizeof(float);  // 98,816 B
    cudaFuncSetAttribute(caps_route_kernel,
                         cudaFuncAttributeMaxDynamicSharedMemorySize, (int)smem);
    caps_route_kernel<<<B_, T_, smem>>>(x, W, out);
}

// round 13
// speedup vs baseline: 1.1620x; 1.1620x over previous
#include <cuda_runtime.h>

// CapsNet dynamic routing, factorized. 1 batch/CTA, T=512, 2 CTAs/SM.
// R13 = R11 layout (proven) + packed f32x2 FMA (fma.rn.f32x2) in P2/P3/P6.

namespace {
constexpr int O_ = 10, U_ = 36, E_ = 16, F_ = 8;
constexpr int N_ = 1152;
constexpr int B_ = 256;
constexpr int T_ = 512;              // 16 warps, 2 CTAs/SM
constexpr int NP = 1157;             // c plane stride

// shared layout (floats)
constexpr int OFF_XS = 0;                    // swizzled x [N][F]       9216
constexpr int OFF_C  = OFF_XS + N_ * F_;     // c [O][NP]              11570
constexpr int OFF_P  = (OFF_C + O_ * NP + 3) & ~3;  // pb 720 float4 (16B-aligned)
constexpr int OFF_VV = OFF_P + 2880;         // [O][E]                   160
constexpr int SM_FLOATS = OFF_VV + 160;      // -> 95,312 B
} // namespace

using ull = unsigned long long;

__device__ __forceinline__ int xsw(int i) { return i ^ ((i >> 3) & 7); }

__device__ __forceinline__ ull pack2(float lo, float hi) {
    ull r; asm("mov.b64 %0, {%1, %2};" : "=l"(r) : "f"(lo), "f"(hi)); return r;
}
__device__ __forceinline__ void unpack2(ull v, float& lo, float& hi) {
    asm("mov.b64 {%0, %1}, %2;" : "=f"(lo), "=f"(hi) : "l"(v));
}
__device__ __forceinline__ ull fma2(ull a, ull b, ull c) {
    ull d; asm("fma.rn.f32x2 %0, %1, %2, %3;" : "=l"(d) : "l"(a), "l"(b), "l"(c)); return d;
}
__device__ __forceinline__ ull add2(ull a, ull b) {
    ull d; asm("add.rn.f32x2 %0, %1, %2;" : "=l"(d) : "l"(a), "l"(b)); return d;
}
__device__ __forceinline__ ull mul2(ull a, ull b) {
    ull d; asm("mul.rn.f32x2 %0, %1, %2;" : "=l"(d) : "l"(a), "l"(b)); return d;
}

__global__ __launch_bounds__(T_, 2)
void caps_route_kernel(const float* __restrict__ x,
                       const float* __restrict__ Wg,
                       float* __restrict__ out) {
    extern __shared__ float sm[];
    float* cc  = sm + OFF_C;
    float* pbf = sm + OFF_P;
    float* vv  = sm + OFF_VV;
    float4* xs4 = reinterpret_cast<float4*>(sm + OFF_XS);
    float4* pb4 = reinterpret_cast<float4*>(pbf);

    const int tid = threadIdx.x;
    const int b = blockIdx.x;
    const int warp = tid >> 5;
    const int lane = tid & 31;

    const float4* __restrict__ wp4 = reinterpret_cast<const float4*>(Wg);

    // ---- load x tile (coalesced gmem read, swizzled smem store) ----
    {
        const float4* xg = reinterpret_cast<const float4*>(x) + (size_t)b * (N_ * F_ / 4);
        #pragma unroll
        for (int i = tid; i < N_ * F_ / 4; i += T_) xs4[xsw(i)] = xg[i];
    }
    __syncthreads();

    // P2 task decode (288 tasks): tid = u<<3 | oh<<2 | fg<<1 | sh  (sh = lane bit 0)
    const int p2_sh = tid & 1;
    const int p2_fg = (tid >> 1) & 1;
    const int p2_oh = (tid >> 2) & 1;
    const int p2_u  = tid >> 3;
    const float* p2_cb = cc + p2_oh * 5 * NP + p2_u * 33 - p2_u * 33 + p2_oh * 0; // placeholder (see below)
    // NOTE: layout identical to R11: c index = (oh*5+o')*NP + u*32 + sh*16 + s
    const float* p2_cbase = cc + p2_oh * 5 * NP + p2_u * 32 + p2_sh * 16;
    const int p2_pbase = (p2_u * 32 + p2_sh * 16) * 2 + p2_fg;
    float4* p2_pr = pb4 + (tid >> 1) * 5;    // task' = (u,oh,fg), sh reduced away

    // P3 decode: warp = o (<10); lane = e*2 + fh (lane-linear W)
    const int p3_e  = lane >> 1;
    const int p3_fh = lane & 1;

    // P5 decode
    const int p5_e  = lane >> 1;
    const int sel1 = (lane >> 1) & 1;
    const int sel2 = (lane >> 2) & 1;
    const int p5_f = (lane & 1) * 4 + sel1 * 2 + sel2;

    for (int it = 0; it < 4; ++it) {
        // ---- P2: y partials for (u,fg,oh); f32x2 FMA; sh halves merged via shfl ----
        if (tid < 288) {
            ull acc[10];
            #pragma unroll
            for (int r = 0; r < 10; ++r) acc[r] = 0ull;   // (0.f, 0.f)
            if (it == 0) {
                ull sA = 0ull, sB = 0ull;
                #pragma unroll
                for (int j = 0; j < 16; ++j) {
                    const ulonglong2 xv =
                        *reinterpret_cast<const ulonglong2*>(&xs4[xsw(p2_pbase + 2 * j)]);
                    sA = add2(sA, xv.x);
                    sB = add2(sB, xv.y);
                }
                const ull tenth = pack2(0.1f, 0.1f);
                sA = mul2(sA, tenth);
                sB = mul2(sB, tenth);
                #pragma unroll
                for (int oi = 0; oi < 5; ++oi) { acc[2 * oi] = sA; acc[2 * oi + 1] = sB; }
            } else {
                #pragma unroll
                for (int j = 0; j < 16; ++j) {
                    const int s = (p2_u + j) & 15;          // rotation: spread banks
                    const ulonglong2 xv =
                        *reinterpret_cast<const ulonglong2*>(&xs4[xsw(p2_pbase + 2 * s)]);
                    #pragma unroll
                    for (int oi = 0; oi < 5; ++oi) {
                        const float cv = p2_cbase[oi * NP + s];
                        const ull c2 = pack2(cv, cv);
                        acc[2 * oi]     = fma2(c2, xv.x, acc[2 * oi]);
                        acc[2 * oi + 1] = fma2(c2, xv.y, acc[2 * oi + 1]);
                    }
                }
            }
            // merge sh halves (lane bit 0) in packed form
            #pragma unroll
            for (int r = 0; r < 10; ++r)
                acc[r] = add2(acc[r], __shfl_xor_sync(0xffffffffu, acc[r], 1));
            if (p2_sh == 0) {
                ulonglong2* pr = reinterpret_cast<ulonglong2*>(p2_pr);
                #pragma unroll
                for (int oi = 0; oi < 5; ++oi) {
                    ulonglong2 v;
                    v.x = acc[2 * oi];
                    v.y = acc[2 * oi + 1];
                    pr[oi] = v;
                }
            }
        }
        __syncthreads();

        // ---- P3 (+fused squash): warp=o, lane=(e,fh), lane-linear W, f32x2 ----
        if (warp < 10) {
            const int o = warp;
            const int oh = (o >= 5);
            const int k = o - 5 * oh;
            const int rbase = (oh * 2 + p3_fh) * 5 + k;
            const ulonglong2* wp = reinterpret_cast<const ulonglong2*>(wp4 + o * 36 * 32 + lane);
            ull acc = 0ull;
            #pragma unroll 6
            for (int u = 0; u < 36; ++u) {
                const ulonglong2 w = wp[u * 32];   // contiguous 512B/warp
                const ulonglong2 A =
                    *reinterpret_cast<const ulonglong2*>(&pb4[u * 20 + rbase]);
                acc = fma2(w.x, A.x, acc);
                acc = fma2(w.y, A.y, acc);
            }
            float plo, phi;
            unpack2(acc, plo, phi);
            const float p0 = plo + phi;
            const float s0 = p0 + __shfl_xor_sync(0xffffffffu, p0, 1);
            float nsq0 = s0 * s0;
            #pragma unroll
            for (int m = 2; m <= 16; m <<= 1)
                nsq0 += __shfl_xor_sync(0xffffffffu, nsq0, m);
            if (p3_fh == 0) vv[o * 16 + p3_e] = s0 * (sqrtf(nsq0) / (1.f + nsq0));
        }
        __syncthreads();

        if (it == 3) break;

        // ---- P5: wv[o,u,f]; warp per (o,u), lane-linear W, shuffle-reduce e ----
        for (int task = warp; task < 360; task += 16) {
            const float4 w = wp4[task * 32 + lane];   // contiguous 512B/warp
            const int o = task / 36;
            const float ve0 = vv[o * 16 + p5_e];
            float P0[4] = {w.x * ve0, w.y * ve0, w.z * ve0, w.w * ve0};
            float k0a = P0[2 * sel1]     + __shfl_xor_sync(0xffffffffu, P0[2 * (sel1 ^ 1)],     2);
            float k0b = P0[2 * sel1 + 1] + __shfl_xor_sync(0xffffffffu, P0[2 * (sel1 ^ 1) + 1], 2);
            float r0 = (sel2 ? k0b : k0a) + __shfl_xor_sync(0xffffffffu, (sel2 ? k0a : k0b), 4);
            r0 += __shfl_xor_sync(0xffffffffu, r0, 8);
            r0 += __shfl_xor_sync(0xffffffffu, r0, 16);
            if (lane < 8) pbf[task * 8 + p5_f] = r0;
        }
        __syncthreads();

        // ---- P6: c <- normalize_o( c * exp(x . wv) ); f32x2 dots ----
        #pragma unroll
        for (int kk = 0; kk < 3; ++kk) {
            const int n = tid + T_ * kk;
            if (n < N_) {
                const int u = n >> 5;
                const int q = xsw(n * 2);
                const ulonglong2 x0 = *reinterpret_cast<const ulonglong2*>(&xs4[q]);
                const ulonglong2 x1 = *reinterpret_cast<const ulonglong2*>(&xs4[q ^ 1]);
                const float4* wvb = pb4 + u * 2;
                float* cp = cc + n;
                float t[O_];
                float ss = 0.f;
                if (it > 0) {
                    #pragma unroll
                    for (int o = 0; o < O_; ++o) t[o] = cp[o * NP];   // issue loads early
                }
                #pragma unroll
                for (int o = 0; o < O_; ++o) {
                    const ulonglong2 wA = *reinterpret_cast<const ulonglong2*>(&wvb[o * 72]);
                    const ulonglong2 wB = *reinterpret_cast<const ulonglong2*>(&wvb[o * 72 + 1]);
                    ull accd = mul2(x0.x, wA.x);
                    accd = fma2(x0.y, wA.y, accd);
                    accd = fma2(x1.x, wB.x, accd);
                    accd = fma2(x1.y, wB.y, accd);
                    float dlo, dhi;
                    unpack2(accd, dlo, dhi);
                    const float d = dlo + dhi;
                    const float tv = (it == 0 ? 0.1f : t[o]) * __expf(d);
                    t[o] = tv;
                    ss += tv;
                }
                const float inv = 1.0f / ss;
                #pragma unroll
                for (int o = 0; o < O_; ++o) cp[o * NP] = t[o] * inv;
            }
        }
        __syncthreads();
    }

    // ---- write out[b][o][e] ----
    if (tid < O_ * E_) {
        out[(size_t)b * (O_ * E_) + tid] = vv[tid];
    }
    (void)p2_cb;
}

extern "C" void kernel_launch(void* const* d_in, const int* in_sizes, int n_in,
                              void* d_out, int out_size) {
    (void)in_sizes; (void)n_in; (void)out_size;
    const float* x = (const float*)d_in[0];
    const float* W = (const float*)d_in[1];
    float* out = (float*)d_out;

    const size_t smem = (size_t)SM_FLOATS * sizeof(float);  // 95,312 B
    cudaFuncSetAttribute(caps_route_kernel,
                         cudaFuncAttributeMaxDynamicSharedMemorySize, (int)smem);
    caps_route_kernel<<<B_, T_, smem>>>(x, W, out);
}

// round 14
// speedup vs baseline: 1.2639x; 1.0877x over previous
#include <cuda_runtime.h>

// CapsNet dynamic routing, factorized. 1 batch/CTA, T=512, 2 CTAs/SM.
// R14 = R13 + paired-task P5 (two (o,u) tasks per warp round, 3-level fold).

namespace {
constexpr int O_ = 10, U_ = 36, E_ = 16, F_ = 8;
constexpr int N_ = 1152;
constexpr int B_ = 256;
constexpr int T_ = 512;              // 16 warps, 2 CTAs/SM
constexpr int NP = 1157;             // c plane stride

// shared layout (floats)
constexpr int OFF_XS = 0;                    // swizzled x [N][F]       9216
constexpr int OFF_C  = OFF_XS + N_ * F_;     // c [O][NP]              11570
constexpr int OFF_P  = (OFF_C + O_ * NP + 3) & ~3;  // pb 720 float4 (16B-aligned)
constexpr int OFF_VV = OFF_P + 2880;         // [O][E]                   160
constexpr int SM_FLOATS = OFF_VV + 160;      // -> 95,312 B
} // namespace

using ull = unsigned long long;

__device__ __forceinline__ int xsw(int i) { return i ^ ((i >> 3) & 7); }

__device__ __forceinline__ ull pack2(float lo, float hi) {
    ull r; asm("mov.b64 %0, {%1, %2};" : "=l"(r) : "f"(lo), "f"(hi)); return r;
}
__device__ __forceinline__ void unpack2(ull v, float& lo, float& hi) {
    asm("mov.b64 {%0, %1}, %2;" : "=f"(lo), "=f"(hi) : "l"(v));
}
__device__ __forceinline__ ull fma2(ull a, ull b, ull c) {
    ull d; asm("fma.rn.f32x2 %0, %1, %2, %3;" : "=l"(d) : "l"(a), "l"(b), "l"(c)); return d;
}
__device__ __forceinline__ ull add2(ull a, ull b) {
    ull d; asm("add.rn.f32x2 %0, %1, %2;" : "=l"(d) : "l"(a), "l"(b)); return d;
}
__device__ __forceinline__ ull mul2(ull a, ull b) {
    ull d; asm("mul.rn.f32x2 %0, %1, %2;" : "=l"(d) : "l"(a), "l"(b)); return d;
}

__global__ __launch_bounds__(T_, 2)
void caps_route_kernel(const float* __restrict__ x,
                       const float* __restrict__ Wg,
                       float* __restrict__ out) {
    extern __shared__ float sm[];
    float* cc  = sm + OFF_C;
    float* pbf = sm + OFF_P;
    float* vv  = sm + OFF_VV;
    float4* xs4 = reinterpret_cast<float4*>(sm + OFF_XS);
    float4* pb4 = reinterpret_cast<float4*>(pbf);

    const int tid = threadIdx.x;
    const int b = blockIdx.x;
    const int warp = tid >> 5;
    const int lane = tid & 31;

    const float4* __restrict__ wp4 = reinterpret_cast<const float4*>(Wg);
    const ulonglong2* __restrict__ wpu = reinterpret_cast<const ulonglong2*>(Wg);

    // ---- load x tile (coalesced gmem read, swizzled smem store) ----
    {
        const float4* xg = reinterpret_cast<const float4*>(x) + (size_t)b * (N_ * F_ / 4);
        #pragma unroll
        for (int i = tid; i < N_ * F_ / 4; i += T_) xs4[xsw(i)] = xg[i];
    }
    __syncthreads();

    // P2 task decode (288 tasks): tid = u<<3 | oh<<2 | fg<<1 | sh  (sh = lane bit 0)
    const int p2_sh = tid & 1;
    const int p2_fg = (tid >> 1) & 1;
    const int p2_oh = (tid >> 2) & 1;
    const int p2_u  = tid >> 3;
    const float* p2_cbase = cc + p2_oh * 5 * NP + p2_u * 32 + p2_sh * 16;
    const int p2_pbase = (p2_u * 32 + p2_sh * 16) * 2 + p2_fg;
    float4* p2_pr = pb4 + (tid >> 1) * 5;    // task' = (u,oh,fg), sh reduced away

    // P3 decode: warp = o (<10); lane = e*2 + fh (lane-linear W)
    const int p3_e  = lane >> 1;
    const int p3_fh = lane & 1;

    // P5 decode: half-warp per task; lanep = e8*2 + fh
    const int p5_th = lane >> 4;          // task half (0/1)
    const int p5_lp = lane & 15;
    const int p5_e8 = p5_lp >> 1;
    const int p5_fh = p5_lp & 1;
    const int p5_s1 = (lane >> 1) & 1;
    const int p5_s2 = (lane >> 2) & 1;
    const int p5_f  = p5_fh * 4 + p5_s1 * 2 + p5_s2;

    for (int it = 0; it < 4; ++it) {
        // ---- P2: y partials for (u,fg,oh); f32x2 FMA; sh halves merged via shfl ----
        if (tid < 288) {
            ull acc[10];
            #pragma unroll
            for (int r = 0; r < 10; ++r) acc[r] = 0ull;   // (0.f, 0.f)
            if (it == 0) {
                ull sA = 0ull, sB = 0ull;
                #pragma unroll
                for (int j = 0; j < 16; ++j) {
                    const ulonglong2 xv =
                        *reinterpret_cast<const ulonglong2*>(&xs4[xsw(p2_pbase + 2 * j)]);
                    sA = add2(sA, xv.x);
                    sB = add2(sB, xv.y);
                }
                const ull tenth = pack2(0.1f, 0.1f);
                sA = mul2(sA, tenth);
                sB = mul2(sB, tenth);
                #pragma unroll
                for (int oi = 0; oi < 5; ++oi) { acc[2 * oi] = sA; acc[2 * oi + 1] = sB; }
            } else {
                #pragma unroll
                for (int j = 0; j < 16; ++j) {
                    const int s = (p2_u + j) & 15;          // rotation: spread banks
                    const ulonglong2 xv =
                        *reinterpret_cast<const ulonglong2*>(&xs4[xsw(p2_pbase + 2 * s)]);
                    #pragma unroll
                    for (int oi = 0; oi < 5; ++oi) {
                        const float cv = p2_cbase[oi * NP + s];
                        const ull c2 = pack2(cv, cv);
                        acc[2 * oi]     = fma2(c2, xv.x, acc[2 * oi]);
                        acc[2 * oi + 1] = fma2(c2, xv.y, acc[2 * oi + 1]);
                    }
                }
            }
            // merge sh halves (lane bit 0) in packed form
            #pragma unroll
            for (int r = 0; r < 10; ++r)
                acc[r] = add2(acc[r], __shfl_xor_sync(0xffffffffu, acc[r], 1));
            if (p2_sh == 0) {
                ulonglong2* pr = reinterpret_cast<ulonglong2*>(p2_pr);
                #pragma unroll
                for (int oi = 0; oi < 5; ++oi) {
                    ulonglong2 v;
                    v.x = acc[2 * oi];
                    v.y = acc[2 * oi + 1];
                    pr[oi] = v;
                }
            }
        }
        __syncthreads();

        // ---- P3 (+fused squash): warp=o, lane=(e,fh), lane-linear W, f32x2 ----
        if (warp < 10) {
            const int o = warp;
            const int oh = (o >= 5);
            const int k = o - 5 * oh;
            const int rbase = (oh * 2 + p3_fh) * 5 + k;
            const ulonglong2* wp = wpu + o * 36 * 32 + lane;
            ull acc = 0ull;
            #pragma unroll 6
            for (int u = 0; u < 36; ++u) {
                const ulonglong2 w = wp[u * 32];   // contiguous 512B/warp
                const ulonglong2 A =
                    *reinterpret_cast<const ulonglong2*>(&pb4[u * 20 + rbase]);
                acc = fma2(w.x, A.x, acc);
                acc = fma2(w.y, A.y, acc);
            }
            float plo, phi;
            unpack2(acc, plo, phi);
            const float p0 = plo + phi;
            const float s0 = p0 + __shfl_xor_sync(0xffffffffu, p0, 1);
            float nsq0 = s0 * s0;
            #pragma unroll
            for (int m = 2; m <= 16; m <<= 1)
                nsq0 += __shfl_xor_sync(0xffffffffu, nsq0, m);
            if (p3_fh == 0) vv[o * 16 + p3_e] = s0 * (sqrtf(nsq0) / (1.f + nsq0));
        }
        __syncthreads();

        if (it == 3) break;

        // ---- P5: wv[o,u,f]; TWO tasks per warp round (one per 16-lane half).
        // Lane (e8,fh) accumulates e and e+8 contributions, 3-level fold. ----
        for (int pi = warp; pi < 180; pi += 16) {
            const int task = pi * 2 + p5_th;
            const ulonglong2 w0 = wpu[task * 32 + p5_lp];        // e = e8
            const ulonglong2 w1 = wpu[task * 32 + 16 + p5_lp];   // e = e8+8
            const int o = task / 36;
            const float v0 = vv[o * 16 + p5_e8];
            const float v1 = vv[o * 16 + 8 + p5_e8];
            const ull v0p = pack2(v0, v0);
            const ull v1p = pack2(v1, v1);
            ull acc01 = fma2(w0.x, v0p, mul2(w1.x, v1p));   // f = fh*4 + {0,1}
            ull acc23 = fma2(w0.y, v0p, mul2(w1.y, v1p));   // f = fh*4 + {2,3}
            // fold xor2 (e8 bit0): keep own f-pair type, receive partner's
            const ull keep1 = p5_s1 ? acc23 : acc01;
            const ull send1 = p5_s1 ? acc01 : acc23;
            const ull r1 = add2(keep1, __shfl_xor_sync(0xffffffffu, send1, 2));
            // fold xor4 (e8 bit1): 2 floats -> 1
            float rlo, rhi;
            unpack2(r1, rlo, rhi);
            const float keep2 = p5_s2 ? rhi : rlo;
            const float send2 = p5_s2 ? rlo : rhi;
            float r2 = keep2 + __shfl_xor_sync(0xffffffffu, send2, 4);
            // xor8 (e8 bit2): full sum
            r2 += __shfl_xor_sync(0xffffffffu, r2, 8);
            if (p5_lp < 8) pbf[task * 8 + p5_f] = r2;
        }
        __syncthreads();

        // ---- P6: c <- normalize_o( c * exp(x . wv) ); f32x2 dots ----
        #pragma unroll
        for (int kk = 0; kk < 3; ++kk) {
            const int n = tid + T_ * kk;
            if (n < N_) {
                const int u = n >> 5;
                const int q = xsw(n * 2);
                const ulonglong2 x0 = *reinterpret_cast<const ulonglong2*>(&xs4[q]);
                const ulonglong2 x1 = *reinterpret_cast<const ulonglong2*>(&xs4[q ^ 1]);
                const float4* wvb = pb4 + u * 2;
                float* cp = cc + n;
                float t[O_];
                float ss = 0.f;
                if (it > 0) {
                    #pragma unroll
                    for (int o = 0; o < O_; ++o) t[o] = cp[o * NP];   // issue loads early
                }
                #pragma unroll
                for (int o = 0; o < O_; ++o) {
                    const ulonglong2 wA = *reinterpret_cast<const ulonglong2*>(&wvb[o * 72]);
                    const ulonglong2 wB = *reinterpret_cast<const ulonglong2*>(&wvb[o * 72 + 1]);
                    ull accd = mul2(x0.x, wA.x);
                    accd = fma2(x0.y, wA.y, accd);
                    accd = fma2(x1.x, wB.x, accd);
                    accd = fma2(x1.y, wB.y, accd);
                    float dlo, dhi;
                    unpack2(accd, dlo, dhi);
                    const float d = dlo + dhi;
                    const float tv = (it == 0 ? 0.1f : t[o]) * __expf(d);
                    t[o] = tv;
                    ss += tv;
                }
                const float inv = 1.0f / ss;
                #pragma unroll
                for (int o = 0; o < O_; ++o) cp[o * NP] = t[o] * inv;
            }
        }
        __syncthreads();
    }

    // ---- write out[b][o][e] ----
    if (tid < O_ * E_) {
        out[(size_t)b * (O_ * E_) + tid] = vv[tid];
    }
}

extern "C" void kernel_launch(void* const* d_in, const int* in_sizes, int n_in,
                              void* d_out, int out_size) {
    (void)in_sizes; (void)n_in; (void)out_size;
    const float* x = (const float*)d_in[0];
    const float* W = (const float*)d_in[1];
    float* out = (float*)d_out;

    const size_t smem = (size_t)SM_FLOATS * sizeof(float);  // 95,312 B
    cudaFuncSetAttribute(caps_route_kernel,
                         cudaFuncAttributeMaxDynamicSharedMemorySize, (int)smem);
    caps_route_kernel<<<B_, T_, smem>>>(x, W, out);
}

// round 15
// speedup vs baseline: 1.2732x; 1.0074x over previous
#include <cuda_runtime.h>

// CapsNet dynamic routing, factorized. 1 batch/CTA, T=512, 2 CTAs/SM.
// R15 = R14 + latency scheduling: P3 unroll12/dual-acc, P6 dual-chain dot,
// P5 unroll2.

namespace {
constexpr int O_ = 10, U_ = 36, E_ = 16, F_ = 8;
constexpr int N_ = 1152;
constexpr int B_ = 256;
constexpr int T_ = 512;              // 16 warps, 2 CTAs/SM
constexpr int NP = 1157;             // c plane stride

// shared layout (floats)
constexpr int OFF_XS = 0;                    // swizzled x [N][F]       9216
constexpr int OFF_C  = OFF_XS + N_ * F_;     // c [O][NP]              11570
constexpr int OFF_P  = (OFF_C + O_ * NP + 3) & ~3;  // pb 720 float4 (16B-aligned)
constexpr int OFF_VV = OFF_P + 2880;         // [O][E]                   160
constexpr int SM_FLOATS = OFF_VV + 160;      // -> 95,312 B
} // namespace

using ull = unsigned long long;

__device__ __forceinline__ int xsw(int i) { return i ^ ((i >> 3) & 7); }

__device__ __forceinline__ ull pack2(float lo, float hi) {
    ull r; asm("mov.b64 %0, {%1, %2};" : "=l"(r) : "f"(lo), "f"(hi)); return r;
}
__device__ __forceinline__ void unpack2(ull v, float& lo, float& hi) {
    asm("mov.b64 {%0, %1}, %2;" : "=f"(lo), "=f"(hi) : "l"(v));
}
__device__ __forceinline__ ull fma2(ull a, ull b, ull c) {
    ull d; asm("fma.rn.f32x2 %0, %1, %2, %3;" : "=l"(d) : "l"(a), "l"(b), "l"(c)); return d;
}
__device__ __forceinline__ ull add2(ull a, ull b) {
    ull d; asm("add.rn.f32x2 %0, %1, %2;" : "=l"(d) : "l"(a), "l"(b)); return d;
}
__device__ __forceinline__ ull mul2(ull a, ull b) {
    ull d; asm("mul.rn.f32x2 %0, %1, %2;" : "=l"(d) : "l"(a), "l"(b)); return d;
}

__global__ __launch_bounds__(T_, 2)
void caps_route_kernel(const float* __restrict__ x,
                       const float* __restrict__ Wg,
                       float* __restrict__ out) {
    extern __shared__ float sm[];
    float* cc  = sm + OFF_C;
    float* pbf = sm + OFF_P;
    float* vv  = sm + OFF_VV;
    float4* xs4 = reinterpret_cast<float4*>(sm + OFF_XS);
    float4* pb4 = reinterpret_cast<float4*>(pbf);

    const int tid = threadIdx.x;
    const int b = blockIdx.x;
    const int warp = tid >> 5;
    const int lane = tid & 31;

    const float4* __restrict__ wp4 = reinterpret_cast<const float4*>(Wg);
    const ulonglong2* __restrict__ wpu = reinterpret_cast<const ulonglong2*>(Wg);

    // ---- load x tile (coalesced gmem read, swizzled smem store) ----
    {
        const float4* xg = reinterpret_cast<const float4*>(x) + (size_t)b * (N_ * F_ / 4);
        #pragma unroll
        for (int i = tid; i < N_ * F_ / 4; i += T_) xs4[xsw(i)] = xg[i];
    }
    __syncthreads();

    // P2 task decode (288 tasks): tid = u<<3 | oh<<2 | fg<<1 | sh  (sh = lane bit 0)
    const int p2_sh = tid & 1;
    const int p2_fg = (tid >> 1) & 1;
    const int p2_oh = (tid >> 2) & 1;
    const int p2_u  = tid >> 3;
    const float* p2_cbase = cc + p2_oh * 5 * NP + p2_u * 32 + p2_sh * 16;
    const int p2_pbase = (p2_u * 32 + p2_sh * 16) * 2 + p2_fg;
    float4* p2_pr = pb4 + (tid >> 1) * 5;    // task' = (u,oh,fg), sh reduced away

    // P3 decode: warp = o (<10); lane = e*2 + fh (lane-linear W)
    const int p3_e  = lane >> 1;
    const int p3_fh = lane & 1;

    // P5 decode: half-warp per task; lanep = e8*2 + fh
    const int p5_th = lane >> 4;          // task half (0/1)
    const int p5_lp = lane & 15;
    const int p5_e8 = p5_lp >> 1;
    const int p5_fh = p5_lp & 1;
    const int p5_s1 = (lane >> 1) & 1;
    const int p5_s2 = (lane >> 2) & 1;
    const int p5_f  = p5_fh * 4 + p5_s1 * 2 + p5_s2;

    for (int it = 0; it < 4; ++it) {
        // ---- P2: y partials for (u,fg,oh); f32x2 FMA; sh halves merged via shfl ----
        if (tid < 288) {
            ull acc[10];
            #pragma unroll
            for (int r = 0; r < 10; ++r) acc[r] = 0ull;   // (0.f, 0.f)
            if (it == 0) {
                ull sA = 0ull, sB = 0ull;
                #pragma unroll
                for (int j = 0; j < 16; ++j) {
                    const ulonglong2 xv =
                        *reinterpret_cast<const ulonglong2*>(&xs4[xsw(p2_pbase + 2 * j)]);
                    sA = add2(sA, xv.x);
                    sB = add2(sB, xv.y);
                }
                const ull tenth = pack2(0.1f, 0.1f);
                sA = mul2(sA, tenth);
                sB = mul2(sB, tenth);
                #pragma unroll
                for (int oi = 0; oi < 5; ++oi) { acc[2 * oi] = sA; acc[2 * oi + 1] = sB; }
            } else {
                #pragma unroll
                for (int j = 0; j < 16; ++j) {
                    const int s = (p2_u + j) & 15;          // rotation: spread banks
                    const ulonglong2 xv =
                        *reinterpret_cast<const ulonglong2*>(&xs4[xsw(p2_pbase + 2 * s)]);
                    #pragma unroll
                    for (int oi = 0; oi < 5; ++oi) {
                        const float cv = p2_cbase[oi * NP + s];
                        const ull c2 = pack2(cv, cv);
                        acc[2 * oi]     = fma2(c2, xv.x, acc[2 * oi]);
                        acc[2 * oi + 1] = fma2(c2, xv.y, acc[2 * oi + 1]);
                    }
                }
            }
            // merge sh halves (lane bit 0) in packed form
            #pragma unroll
            for (int r = 0; r < 10; ++r)
                acc[r] = add2(acc[r], __shfl_xor_sync(0xffffffffu, acc[r], 1));
            if (p2_sh == 0) {
                ulonglong2* pr = reinterpret_cast<ulonglong2*>(p2_pr);
                #pragma unroll
                for (int oi = 0; oi < 5; ++oi) {
                    ulonglong2 v;
                    v.x = acc[2 * oi];
                    v.y = acc[2 * oi + 1];
                    pr[oi] = v;
                }
            }
        }
        __syncthreads();

        // ---- P3 (+fused squash): warp=o, lane=(e,fh), lane-linear W, f32x2,
        //      unroll 12 + dual accumulators for LDG MLP / shorter fma chain ----
        if (warp < 10) {
            const int o = warp;
            const int oh = (o >= 5);
            const int k = o - 5 * oh;
            const int rbase = (oh * 2 + p3_fh) * 5 + k;
            const ulonglong2* wp = wpu + o * 36 * 32 + lane;
            ull accA = 0ull, accB = 0ull;
            #pragma unroll 12
            for (int u = 0; u < 36; u += 2) {
                const ulonglong2 w0 = wp[u * 32];
                const ulonglong2 w1 = wp[(u + 1) * 32];
                const ulonglong2 A0 =
                    *reinterpret_cast<const ulonglong2*>(&pb4[u * 20 + rbase]);
                const ulonglong2 A1 =
                    *reinterpret_cast<const ulonglong2*>(&pb4[(u + 1) * 20 + rbase]);
                accA = fma2(w0.x, A0.x, accA);
                accB = fma2(w0.y, A0.y, accB);
                accA = fma2(w1.x, A1.x, accA);
                accB = fma2(w1.y, A1.y, accB);
            }
            const ull accT = add2(accA, accB);
            float plo, phi;
            unpack2(accT, plo, phi);
            const float p0 = plo + phi;
            const float s0 = p0 + __shfl_xor_sync(0xffffffffu, p0, 1);
            float nsq0 = s0 * s0;
            #pragma unroll
            for (int m = 2; m <= 16; m <<= 1)
                nsq0 += __shfl_xor_sync(0xffffffffu, nsq0, m);
            if (p3_fh == 0) vv[o * 16 + p3_e] = s0 * (sqrtf(nsq0) / (1.f + nsq0));
        }
        __syncthreads();

        if (it == 3) break;

        // ---- P5: wv[o,u,f]; TWO tasks per warp round (one per 16-lane half).
        // Lane (e8,fh) accumulates e and e+8 contributions, 3-level fold. ----
        #pragma unroll 2
        for (int pi = warp; pi < 180; pi += 16) {
            const int task = pi * 2 + p5_th;
            const ulonglong2 w0 = wpu[task * 32 + p5_lp];        // e = e8
            const ulonglong2 w1 = wpu[task * 32 + 16 + p5_lp];   // e = e8+8
            const int o = task / 36;
            const float v0 = vv[o * 16 + p5_e8];
            const float v1 = vv[o * 16 + 8 + p5_e8];
            const ull v0p = pack2(v0, v0);
            const ull v1p = pack2(v1, v1);
            ull acc01 = fma2(w0.x, v0p, mul2(w1.x, v1p));   // f = fh*4 + {0,1}
            ull acc23 = fma2(w0.y, v0p, mul2(w1.y, v1p));   // f = fh*4 + {2,3}
            // fold xor2 (e8 bit0): keep own f-pair type, receive partner's
            const ull keep1 = p5_s1 ? acc23 : acc01;
            const ull send1 = p5_s1 ? acc01 : acc23;
            const ull r1 = add2(keep1, __shfl_xor_sync(0xffffffffu, send1, 2));
            // fold xor4 (e8 bit1): 2 floats -> 1
            float rlo, rhi;
            unpack2(r1, rlo, rhi);
            const float keep2 = p5_s2 ? rhi : rlo;
            const float send2 = p5_s2 ? rlo : rhi;
            float r2 = keep2 + __shfl_xor_sync(0xffffffffu, send2, 4);
            // xor8 (e8 bit2): full sum
            r2 += __shfl_xor_sync(0xffffffffu, r2, 8);
            if (p5_lp < 8) pbf[task * 8 + p5_f] = r2;
        }
        __syncthreads();

        // ---- P6: c <- normalize_o( c * exp(x . wv) ); dual f32x2 chains ----
        #pragma unroll
        for (int kk = 0; kk < 3; ++kk) {
            const int n = tid + T_ * kk;
            if (n < N_) {
                const int u = n >> 5;
                const int q = xsw(n * 2);
                const ulonglong2 x0 = *reinterpret_cast<const ulonglong2*>(&xs4[q]);
                const ulonglong2 x1 = *reinterpret_cast<const ulonglong2*>(&xs4[q ^ 1]);
                const float4* wvb = pb4 + u * 2;
                float* cp = cc + n;
                float t[O_];
                float ss = 0.f;
                if (it > 0) {
                    #pragma unroll
                    for (int o = 0; o < O_; ++o) t[o] = cp[o * NP];   // issue loads early
                }
                #pragma unroll
                for (int o = 0; o < O_; ++o) {
                    const ulonglong2 wA = *reinterpret_cast<const ulonglong2*>(&wvb[o * 72]);
                    const ulonglong2 wB = *reinterpret_cast<const ulonglong2*>(&wvb[o * 72 + 1]);
                    ull d0 = fma2(x0.y, wA.y, mul2(x0.x, wA.x));
                    ull d1 = fma2(x1.y, wB.y, mul2(x1.x, wB.x));
                    const ull dsum = add2(d0, d1);
                    float dlo, dhi;
                    unpack2(dsum, dlo, dhi);
                    const float d = dlo + dhi;
                    const float tv = (it == 0 ? 0.1f : t[o]) * __expf(d);
                    t[o] = tv;
                    ss += tv;
                }
                const float inv = 1.0f / ss;
                #pragma unroll
                for (int o = 0; o < O_; ++o) cp[o * NP] = t[o] * inv;
            }
        }
        __syncthreads();
    }

    // ---- write out[b][o][e] ----
    if (tid < O_ * E_) {
        out[(size_t)b * (O_ * E_) + tid] = vv[tid];
    }
}

extern "C" void kernel_launch(void* const* d_in, const int* in_sizes, int n_in,
                              void* d_out, int out_size) {
    (void)in_sizes; (void)n_in; (void)out_size;
    const float* x = (const float*)d_in[0];
    const float* W = (const float*)d_in[1];
    float* out = (float*)d_out;

    const size_t smem = (size_t)SM_FLOATS * sizeof(float);  // 95,312 B
    cudaFuncSetAttribute(caps_route_kernel,
                         cudaFuncAttributeMaxDynamicSharedMemorySize, (int)smem);
    caps_route_kernel<<<B_, T_, smem>>>(x, W, out);
}